// round 8
// baseline (speedup 1.0000x reference)
#include <cuda_runtime.h>
#include <math.h>

// Problem constants (fixed by the reference)
#define BB      32
#define SS      4096
#define HQN     32
#define HKVN    8
#define GG      4          // HQN / HKVN
#define DD      128
#define NSPLIT  32
#define CHUNK   (SS / NSPLIT)   // 128
#define KVROW   (HKVN * DD)     // 1024 floats between consecutive s rows
#define SCALE_F 0.088388347648318447f   // 1/sqrt(128)
// p = exp(sc - 30), sc = 30*tanh(dot*SCALE/30)  =>  p = exp(-60/(exp(dot*SCALE/15)+1))
#define C2_F    (SCALE_F / 15.0f)

// Split-KV scratch (no allocations -> __device__ globals)
// pacc: [B][HKV][NSPLIT][G][D], pl: [B][HKV][NSPLIT][G]
__device__ float g_pacc[(size_t)BB * HKVN * NSPLIT * GG * DD];
__device__ float g_pl[(size_t)BB * HKVN * NSPLIT * GG];
// last-CTA-reduces counters, one per (b,h). Zero-initialized at module load;
// the reducing CTA resets its counter to 0, so every graph replay sees zeros.
__device__ unsigned int g_cnt[BB * HKVN];

typedef unsigned long long u64;

__device__ __forceinline__ void fma2(u64 &d, u64 a, u64 b) {
    asm("fma.rn.f32x2 %0, %1, %2, %0;" : "+l"(d) : "l"(a), "l"(b));
}
__device__ __forceinline__ u64 pk(float x, float y) {
    u64 r; asm("mov.b64 %0, {%1, %2};" : "=l"(r) : "f"(x), "f"(y)); return r;
}
__device__ __forceinline__ float usum(u64 v) {
    float lo, hi; asm("mov.b64 {%0, %1}, %2;" : "=f"(lo), "=f"(hi) : "l"(v));
    return lo + hi;
}

struct Buf {               // one pipeline stage: this lane's 8 floats of K and V
    u64 k[4];
    u64 v[4];
    bool ok;
};

__device__ __forceinline__ Buf load_buf(const float* __restrict__ kb,
                                        const float* __restrict__ vb,
                                        int s, int end_c)
{
    Buf r;
    r.ok = (s < end_c);
    size_t row = (size_t)(r.ok ? s : (end_c - 1)) * KVROW;
    float4 ka  = __ldcs((const float4*)(kb + row));
    float4 kc4 = __ldcs((const float4*)(kb + row + 4));
    float4 va  = __ldcs((const float4*)(vb + row));
    float4 vc4 = __ldcs((const float4*)(vb + row + 4));
    r.k[0] = pk(ka.x, ka.y);   r.k[1] = pk(ka.z, ka.w);
    r.k[2] = pk(kc4.x, kc4.y); r.k[3] = pk(kc4.z, kc4.w);
    r.v[0] = pk(va.x, va.y);   r.v[1] = pk(va.z, va.w);
    r.v[2] = pk(vc4.x, vc4.y); r.v[3] = pk(vc4.z, vc4.w);
    return r;
}

struct WState {
    u64 q2[GG][4];
    u64 acc[GG][4];
    float l[GG];
};

// Process one s position per half-warp (2 s per warp per call).
__device__ __forceinline__ void body(WState &st, const Buf &bf)
{
    float d[GG];
#pragma unroll
    for (int g = 0; g < GG; g++) {
        u64 t = pk(0.f, 0.f);
        fma2(t, st.q2[g][0], bf.k[0]);
        fma2(t, st.q2[g][1], bf.k[1]);
        fma2(t, st.q2[g][2], bf.k[2]);
        fma2(t, st.q2[g][3], bf.k[3]);
        d[g] = usum(t);
    }
#pragma unroll
    for (int off = 8; off > 0; off >>= 1) {
#pragma unroll
        for (int g = 0; g < GG; g++)
            d[g] += __shfl_xor_sync(0xffffffffu, d[g], off);
    }
#pragma unroll
    for (int g = 0; g < GG; g++) {
        float t = __expf(d[g] * C2_F);
        float p = __expf(__fdividef(-60.0f, t + 1.0f));
        p = bf.ok ? p : 0.0f;
        st.l[g] += p;
        u64 pp = pk(p, p);
        fma2(st.acc[g][0], pp, bf.v[0]);
        fma2(st.acc[g][1], pp, bf.v[1]);
        fma2(st.acc[g][2], pp, bf.v[2]);
        fma2(st.acc[g][3], pp, bf.v[3]);
    }
}

__global__ void __launch_bounds__(128, 4)
attn_fused_kernel(const float* __restrict__ q,
                  const float* __restrict__ knew,
                  const float* __restrict__ vnew,
                  const float* __restrict__ kc,
                  const float* __restrict__ vc,
                  const int*   __restrict__ seq_lens,
                  float*       __restrict__ out)
{
    const int h     = blockIdx.x;        // h fastest: 8 neighbor CTAs share one s-range
    const int split = blockIdx.y;
    const int b     = blockIdx.z;
    const int tid   = threadIdx.x;
    const int w     = tid >> 5;          // 4 warps
    const int lane  = tid & 31;
    const int half  = lane >> 4;
    const int lh    = lane & 15;
    const int dcol  = lh * 8;

    const int seq_len = seq_lens[b];
    const int start   = split * CHUNK;

    // invalid split: nothing to do, never read by the reduction
    if (start >= seq_len) return;

    __shared__ float s_acc[4][GG][DD];
    __shared__ float s_l[4][GG];
    __shared__ unsigned int s_islast;

    const int n_valid = min(NSPLIT, (seq_len + CHUNK - 1) / CHUNK);
    const size_t pbase = (((size_t)(b * HKVN + h) * NSPLIT) + split) * GG;

    WState st;
    {
        const float* qb = q + (size_t)b * HQN * DD + (size_t)h * GG * DD + dcol;
#pragma unroll
        for (int g = 0; g < GG; g++) {
            float4 qa = *(const float4*)(qb + (size_t)g * DD);
            float4 qc = *(const float4*)(qb + (size_t)g * DD + 4);
            st.q2[g][0] = pk(qa.x, qa.y);
            st.q2[g][1] = pk(qa.z, qa.w);
            st.q2[g][2] = pk(qc.x, qc.y);
            st.q2[g][3] = pk(qc.z, qc.w);
            st.acc[g][0] = st.acc[g][1] = st.acc[g][2] = st.acc[g][3] = pk(0.f, 0.f);
            st.l[g] = 0.f;
        }
    }

    // cache rows: s in [start, end_c); s = seq_len-1 comes from knew/vnew instead
    const int end_c = min(start + CHUNK, seq_len - 1);
    const float* kb = kc + ((size_t)b * SS) * KVROW + (size_t)h * DD + dcol;
    const float* vb = vc + ((size_t)b * SS) * KVROW + (size_t)h * DD + dcol;

    const int span = end_c - start;                 // may be <= 0
    const int n_it = (span > 0) ? ((span + 7) >> 3) : 0;
    const int s0   = start + w * 2 + half;

    if (n_it > 0) {
        // depth-2 software pipeline: prefetch iter i+1 before processing iter i
        Buf cur = load_buf(kb, vb, s0, end_c);
        for (int it = 1; it < n_it; it++) {
            Buf nxt = load_buf(kb, vb, s0 + it * 8, end_c);
            body(st, cur);
            cur = nxt;
        }
        body(st, cur);
    }

    // new token (s = seq_len-1), handled once by warp 0 / half 0
    const int last = seq_len - 1;
    if (w == 0 && last >= start && last < start + CHUNK) {
        const float* kp = knew + ((size_t)b * HKVN + h) * DD + dcol;
        const float* vp = vnew + ((size_t)b * HKVN + h) * DD + dcol;
        Buf nb;
        nb.ok = (half == 0);
        float4 ka  = *(const float4*)(kp);
        float4 kc4 = *(const float4*)(kp + 4);
        float4 va  = *(const float4*)(vp);
        float4 vc4 = *(const float4*)(vp + 4);
        nb.k[0] = pk(ka.x, ka.y);   nb.k[1] = pk(ka.z, ka.w);
        nb.k[2] = pk(kc4.x, kc4.y); nb.k[3] = pk(kc4.z, kc4.w);
        nb.v[0] = pk(va.x, va.y);   nb.v[1] = pk(va.z, va.w);
        nb.v[2] = pk(vc4.x, vc4.y); nb.v[3] = pk(vc4.z, vc4.w);
        body(st, nb);
    }

    // fold halves
#pragma unroll
    for (int g = 0; g < GG; g++) {
#pragma unroll
        for (int j = 0; j < 4; j++) {
            u64 o = __shfl_xor_sync(0xffffffffu, st.acc[g][j], 16);
            float2 a = *(float2*)&st.acc[g][j];
            float2 ob = *(float2*)&o;
            a.x += ob.x; a.y += ob.y;
            st.acc[g][j] = pk(a.x, a.y);
        }
        st.l[g] += __shfl_xor_sync(0xffffffffu, st.l[g], 16);
    }

    if (half == 0) {
#pragma unroll
        for (int g = 0; g < GG; g++) {
            u64* dst = (u64*)&s_acc[w][g][dcol];
#pragma unroll
            for (int j = 0; j < 4; j++) dst[j] = st.acc[g][j];
            if (lh == 0) s_l[w][g] = st.l[g];
        }
    }
    __syncthreads();

    // combine 4 warps -> split partial (plain sums; fixed softmax shift m=30)
    for (int i = tid; i < GG * DD; i += 128) {
        int g = i >> 7, d = i & 127;
        float a = s_acc[0][g][d] + s_acc[1][g][d] + s_acc[2][g][d] + s_acc[3][g][d];
        g_pacc[(pbase + g) * DD + d] = a;
    }
    if (tid < GG) {
        float L = s_l[0][tid] + s_l[1][tid] + s_l[2][tid] + s_l[3][tid];
        g_pl[pbase + tid] = L;
    }

    // ---- last-CTA-per-(b,h) reduction ----
    __threadfence();                     // order partial stores before the signal
    __syncthreads();
    if (tid == 0) {
        unsigned int old = atomicAdd(&g_cnt[b * HKVN + h], 1u);
        s_islast = (old == (unsigned int)(n_valid - 1)) ? 1u : 0u;
    }
    __syncthreads();
    if (!s_islast) return;
    __threadfence();                     // acquire side: order peer stores before our loads

    {
        const int g  = tid >> 5;
        const int d4 = (tid & 31) * 4;
        const size_t rbase = ((size_t)(b * HKVN + h) * NSPLIT) * GG + g;

        float denom = 0.f;
        float4 a = make_float4(0.f, 0.f, 0.f, 0.f);
#pragma unroll
        for (int i = 0; i < NSPLIT; i++) {
            bool v = (i < n_valid);
            size_t slot = rbase + (size_t)i * GG;
            float l = v ? g_pl[slot] : 0.f;
            float4 aa = v ? *(const float4*)&g_pacc[slot * DD + d4]
                          : make_float4(0.f, 0.f, 0.f, 0.f);
            denom += l;
            a.x += aa.x; a.y += aa.y; a.z += aa.z; a.w += aa.w;
        }
        float inv = 1.0f / denom;
        float4 o = make_float4(a.x * inv, a.y * inv, a.z * inv, a.w * inv);
        *(float4*)&out[(size_t)b * HQN * DD + (size_t)(h * GG + g) * DD + d4] = o;
    }

    // reset counter for the next graph replay (only we can touch it now)
    if (tid == 0) g_cnt[b * HKVN + h] = 0u;
}

extern "C" void kernel_launch(void* const* d_in, const int* in_sizes, int n_in,
                              void* d_out, int out_size)
{
    const float* q    = (const float*)d_in[0];
    const float* knew = (const float*)d_in[1];
    const float* vnew = (const float*)d_in[2];
    const float* kc   = (const float*)d_in[3];
    const float* vc   = (const float*)d_in[4];
    const int*   sl   = (const int*)  d_in[5];
    float* out = (float*)d_out;

    dim3 grid(HKVN, NSPLIT, BB);
    attn_fused_kernel<<<grid, 128>>>(q, knew, vnew, kc, vc, sl, out);
}

// round 9
// speedup vs baseline: 1.1789x; 1.1789x over previous
#include <cuda_runtime.h>
#include <math.h>
#include <stdint.h>

// Problem constants (fixed by the reference)
#define BB      32
#define SS      4096
#define HQN     32
#define HKVN    8
#define GG      4          // HQN / HKVN
#define DD      128
#define NSPLIT  32
#define CHUNK   (SS / NSPLIT)   // 128
#define KVROW   (HKVN * DD)     // 1024 floats between consecutive s rows
#define SCALE_F 0.088388347648318447f   // 1/sqrt(128)
// p = exp(sc - 30), sc = 30*tanh(dot*SCALE/30)  =>  p = exp(-60/(exp(dot*SCALE/15)+1))
#define C2_F    (SCALE_F / 15.0f)
#define NSTAGE  4          // cp.async pipeline depth (8 KB per stage)

// Split-KV scratch (no allocations -> __device__ globals)
__device__ float g_pacc[(size_t)BB * HKVN * NSPLIT * GG * DD];
__device__ float g_pl[(size_t)BB * HKVN * NSPLIT * GG];

typedef unsigned long long u64;

__device__ __forceinline__ void fma2(u64 &d, u64 a, u64 b) {
    asm("fma.rn.f32x2 %0, %1, %2, %0;" : "+l"(d) : "l"(a), "l"(b));
}
__device__ __forceinline__ u64 pk(float x, float y) {
    u64 r; asm("mov.b64 %0, {%1, %2};" : "=l"(r) : "f"(x), "f"(y)); return r;
}
__device__ __forceinline__ float usum(u64 v) {
    float lo, hi; asm("mov.b64 {%0, %1}, %2;" : "=f"(lo), "=f"(hi) : "l"(v));
    return lo + hi;
}
__device__ __forceinline__ void cp16(uint32_t dst, const void* src) {
    asm volatile("cp.async.cg.shared.global [%0], [%1], 16;" :: "r"(dst), "l"(src));
}
#define CP_COMMIT()  asm volatile("cp.async.commit_group;" ::: "memory")
#define CP_WAIT(N)   asm volatile("cp.async.wait_group %0;" :: "n"(N) : "memory")

struct Buf {
    u64 k[4];
    u64 v[4];
    bool ok;
};

struct WState {
    u64 q2[GG][4];
    u64 acc[GG][4];
    float l[GG];
};

// Process one s position per half-warp (2 s per warp per call).
__device__ __forceinline__ void body(WState &st, const Buf &bf)
{
    float d[GG];
#pragma unroll
    for (int g = 0; g < GG; g++) {
        u64 t = pk(0.f, 0.f);
        fma2(t, st.q2[g][0], bf.k[0]);
        fma2(t, st.q2[g][1], bf.k[1]);
        fma2(t, st.q2[g][2], bf.k[2]);
        fma2(t, st.q2[g][3], bf.k[3]);
        d[g] = usum(t);
    }
#pragma unroll
    for (int off = 8; off > 0; off >>= 1) {
#pragma unroll
        for (int g = 0; g < GG; g++)
            d[g] += __shfl_xor_sync(0xffffffffu, d[g], off);
    }
#pragma unroll
    for (int g = 0; g < GG; g++) {
        float t = __expf(d[g] * C2_F);
        float p = __expf(__fdividef(-60.0f, t + 1.0f));
        p = bf.ok ? p : 0.0f;
        st.l[g] += p;
        u64 pp = pk(p, p);
        fma2(st.acc[g][0], pp, bf.v[0]);
        fma2(st.acc[g][1], pp, bf.v[1]);
        fma2(st.acc[g][2], pp, bf.v[2]);
        fma2(st.acc[g][3], pp, bf.v[3]);
    }
}

__global__ void __launch_bounds__(128, 4)
attn_partial_kernel(const float* __restrict__ q,
                    const float* __restrict__ knew,
                    const float* __restrict__ vnew,
                    const float* __restrict__ kc,
                    const float* __restrict__ vc,
                    const int*   __restrict__ seq_lens)
{
    const int h     = blockIdx.x;
    const int split = blockIdx.y;
    const int b     = blockIdx.z;
    const int tid   = threadIdx.x;
    const int w     = tid >> 5;          // 4 warps
    const int lane  = tid & 31;
    const int half  = lane >> 4;
    const int lh    = lane & 15;
    const int dcol  = lh * 8;

    const int seq_len = seq_lens[b];
    const int start   = split * CHUNK;

    if (start >= seq_len) return;        // never read by the reduce

    // stage layout: [(stage*8+row)*64 + isv*32 + col] float4 -> 32 KB
    __shared__ float4 s_kv[NSTAGE * 8 * 64];
    __shared__ float s_acc[4][GG][DD];
    __shared__ float s_l[4][GG];

    const size_t pbase = (((size_t)(b * HKVN + h) * NSPLIT) + split) * GG;

    WState st;
    {
        const float* qb = q + (size_t)b * HQN * DD + (size_t)h * GG * DD + dcol;
#pragma unroll
        for (int g = 0; g < GG; g++) {
            float4 qa = *(const float4*)(qb + (size_t)g * DD);
            float4 qc = *(const float4*)(qb + (size_t)g * DD + 4);
            st.q2[g][0] = pk(qa.x, qa.y);
            st.q2[g][1] = pk(qa.z, qa.w);
            st.q2[g][2] = pk(qc.x, qc.y);
            st.q2[g][3] = pk(qc.z, qc.w);
            st.acc[g][0] = st.acc[g][1] = st.acc[g][2] = st.acc[g][3] = pk(0.f, 0.f);
            st.l[g] = 0.f;
        }
    }

    const int end_c = min(start + CHUNK, seq_len - 1);   // cache rows only
    const float* kbase = kc + ((size_t)b * SS) * KVROW + (size_t)h * DD;
    const float* vbase = vc + ((size_t)b * SS) * KVROW + (size_t)h * DD;

    const int span = end_c - start;
    const int n_it = (span > 0) ? ((span + 7) >> 3) : 0;

    const uint32_t smem_kv = (uint32_t)__cvta_generic_to_shared(s_kv);

    // cooperative fetch of one stage (8 s rows of K and V, 8 KB), 4 x 16B per thread
#define ISSUE_STAGE(STG, SBASE)                                            \
    do {                                                                   \
        _Pragma("unroll")                                                  \
        for (int j = 0; j < 4; j++) {                                      \
            int ci  = tid + j * 128;        /* 0..511 */                   \
            int row = ci >> 6;                                             \
            int sub = ci & 63;                                             \
            int isv = sub >> 5;                                            \
            int col = sub & 31;                                            \
            int s   = (SBASE) + row;                                       \
            s = (s < end_c) ? s : (end_c - 1);                             \
            const float* srcp = (isv ? vbase : kbase) + (size_t)s * KVROW + col * 4; \
            uint32_t dst = smem_kv + (uint32_t)((((STG) * 8 + row) * 64 + isv * 32 + col) * 16); \
            cp16(dst, srcp);                                               \
        }                                                                  \
    } while (0)

    if (n_it > 0) {
        // prologue: fill NSTAGE-1 stages
#pragma unroll
        for (int p = 0; p < NSTAGE - 1; p++) {
            if (p < n_it) ISSUE_STAGE(p, start + p * 8);
            CP_COMMIT();
        }

        const int row = w * 2 + half;     // this half-warp's row within a stage
        for (int it = 0; it < n_it; it++) {
            CP_WAIT(NSTAGE - 2);
            __syncthreads();

            const int stg = it & (NSTAGE - 1);
            const float4* b4 = s_kv + (stg * 8 + row) * 64;
            float4 k0 = b4[lh * 2], k1 = b4[lh * 2 + 1];
            float4 v0 = b4[32 + lh * 2], v1 = b4[32 + lh * 2 + 1];
            Buf bf;
            bf.ok = (start + it * 8 + row) < end_c;
            bf.k[0] = pk(k0.x, k0.y); bf.k[1] = pk(k0.z, k0.w);
            bf.k[2] = pk(k1.x, k1.y); bf.k[3] = pk(k1.z, k1.w);
            bf.v[0] = pk(v0.x, v0.y); bf.v[1] = pk(v0.z, v0.w);
            bf.v[2] = pk(v1.x, v1.y); bf.v[3] = pk(v1.z, v1.w);
            body(st, bf);

            const int pf = it + NSTAGE - 1;
            if (pf < n_it) ISSUE_STAGE(pf & (NSTAGE - 1), start + pf * 8);
            CP_COMMIT();
        }
    }

    // new token (s = seq_len-1), handled once by warp 0 / half 0
    const int last = seq_len - 1;
    if (w == 0 && last >= start && last < start + CHUNK) {
        const float* kp = knew + ((size_t)b * HKVN + h) * DD + dcol;
        const float* vp = vnew + ((size_t)b * HKVN + h) * DD + dcol;
        Buf nb;
        nb.ok = (half == 0);
        float4 ka  = *(const float4*)(kp);
        float4 kc4 = *(const float4*)(kp + 4);
        float4 va  = *(const float4*)(vp);
        float4 vc4 = *(const float4*)(vp + 4);
        nb.k[0] = pk(ka.x, ka.y);   nb.k[1] = pk(ka.z, ka.w);
        nb.k[2] = pk(kc4.x, kc4.y); nb.k[3] = pk(kc4.z, kc4.w);
        nb.v[0] = pk(va.x, va.y);   nb.v[1] = pk(va.z, va.w);
        nb.v[2] = pk(vc4.x, vc4.y); nb.v[3] = pk(vc4.z, vc4.w);
        body(st, nb);
    }

    // fold halves
#pragma unroll
    for (int g = 0; g < GG; g++) {
#pragma unroll
        for (int j = 0; j < 4; j++) {
            u64 o = __shfl_xor_sync(0xffffffffu, st.acc[g][j], 16);
            float2 a = *(float2*)&st.acc[g][j];
            float2 ob = *(float2*)&o;
            a.x += ob.x; a.y += ob.y;
            st.acc[g][j] = pk(a.x, a.y);
        }
        st.l[g] += __shfl_xor_sync(0xffffffffu, st.l[g], 16);
    }

    if (half == 0) {
#pragma unroll
        for (int g = 0; g < GG; g++) {
            u64* dst = (u64*)&s_acc[w][g][dcol];
#pragma unroll
            for (int j = 0; j < 4; j++) dst[j] = st.acc[g][j];
            if (lh == 0) s_l[w][g] = st.l[g];
        }
    }
    __syncthreads();

    // combine 4 warps -> split partial (plain sums; fixed softmax shift m=30)
    for (int i = tid; i < GG * DD; i += 128) {
        int g = i >> 7, d = i & 127;
        float a = s_acc[0][g][d] + s_acc[1][g][d] + s_acc[2][g][d] + s_acc[3][g][d];
        g_pacc[(pbase + g) * DD + d] = a;
    }
    if (tid < GG) {
        float L = s_l[0][tid] + s_l[1][tid] + s_l[2][tid] + s_l[3][tid];
        g_pl[pbase + tid] = L;
    }
#undef ISSUE_STAGE
}

// One CTA per (b,h,g) = 1024 CTAs. 4 warps split the 32 splits (8 each, predicated,
// fully unrolled -> 16 front-batched loads/thread); one smem combine stage.
__global__ void __launch_bounds__(128)
attn_reduce_kernel(float* __restrict__ out, const int* __restrict__ seq_lens)
{
    const int idx = blockIdx.x;          // [0, BB*HKVN*GG)
    const int g = idx & 3;
    const int h = (idx >> 2) & 7;
    const int b = idx >> 5;
    const int tid  = threadIdx.x;
    const int w    = tid >> 5;
    const int lane = tid & 31;
    const int d4   = lane * 4;

    const int seq_len = seq_lens[b];
    const int n_valid = min(NSPLIT, (seq_len + CHUNK - 1) / CHUNK);

    const size_t base = ((size_t)(b * HKVN + h) * NSPLIT) * GG + g;

    float denom = 0.f;
    float4 a = make_float4(0.f, 0.f, 0.f, 0.f);
#pragma unroll
    for (int it = 0; it < NSPLIT / 4; it++) {
        int i = w + it * 4;
        bool v = (i < n_valid);
        size_t slot = base + (size_t)i * GG;
        float l = v ? g_pl[slot] : 0.f;
        float4 aa = v ? *(const float4*)&g_pacc[slot * DD + d4]
                      : make_float4(0.f, 0.f, 0.f, 0.f);
        denom += l;
        a.x += aa.x; a.y += aa.y; a.z += aa.z; a.w += aa.w;
    }

    __shared__ float4 sa[4][32];
    __shared__ float  sl[4];
    sa[w][lane] = a;
    if (lane == 0) sl[w] = denom;
    __syncthreads();

    if (w == 0) {
        float4 t0 = sa[0][lane], t1 = sa[1][lane], t2 = sa[2][lane], t3 = sa[3][lane];
        float4 t;
        t.x = (t0.x + t1.x) + (t2.x + t3.x);
        t.y = (t0.y + t1.y) + (t2.y + t3.y);
        t.z = (t0.z + t1.z) + (t2.z + t3.z);
        t.w = (t0.w + t1.w) + (t2.w + t3.w);
        float inv = 1.0f / ((sl[0] + sl[1]) + (sl[2] + sl[3]));
        float4 o = make_float4(t.x * inv, t.y * inv, t.z * inv, t.w * inv);
        *(float4*)&out[(size_t)b * HQN * DD + (size_t)(h * GG + g) * DD + d4] = o;
    }
}

extern "C" void kernel_launch(void* const* d_in, const int* in_sizes, int n_in,
                              void* d_out, int out_size)
{
    const float* q    = (const float*)d_in[0];
    const float* knew = (const float*)d_in[1];
    const float* vnew = (const float*)d_in[2];
    const float* kc   = (const float*)d_in[3];
    const float* vc   = (const float*)d_in[4];
    const int*   sl   = (const int*)  d_in[5];
    float* out = (float*)d_out;

    dim3 grid(HKVN, NSPLIT, BB);
    attn_partial_kernel<<<grid, 128>>>(q, knew, vnew, kc, vc, sl);
    attn_reduce_kernel<<<BB * HKVN * GG, 128>>>(out, sl);
}

// round 10
// speedup vs baseline: 1.2052x; 1.0222x over previous
#include <cuda_runtime.h>
#include <math.h>
#include <stdint.h>

// Problem constants (fixed by the reference)
#define BB      32
#define SS      4096
#define HQN     32
#define HKVN    8
#define GG      4          // HQN / HKVN
#define DD      128
#define NSPLIT  32
#define CHUNK   (SS / NSPLIT)   // 128
#define KVROW   (HKVN * DD)     // 1024 floats between consecutive s rows
#define SCALE_F 0.088388347648318447f   // 1/sqrt(128)
// p = exp(sc - 30), sc = 30*tanh(dot*SCALE/30)  =>  p = exp(-60/(exp(dot*SCALE/15)+1))
#define C2_F    (SCALE_F / 15.0f)
#define NSTAGE  4          // cp.async pipeline depth (8 KB per stage)

// Split-KV scratch (no allocations -> __device__ globals)
__device__ float g_pacc[(size_t)BB * HKVN * NSPLIT * GG * DD];
__device__ float g_pl[(size_t)BB * HKVN * NSPLIT * GG];

typedef unsigned long long u64;

__device__ __forceinline__ void fma2(u64 &d, u64 a, u64 b) {
    asm("fma.rn.f32x2 %0, %1, %2, %0;" : "+l"(d) : "l"(a), "l"(b));
}
__device__ __forceinline__ u64 pk(float x, float y) {
    u64 r; asm("mov.b64 %0, {%1, %2};" : "=l"(r) : "f"(x), "f"(y)); return r;
}
__device__ __forceinline__ float usum(u64 v) {
    float lo, hi; asm("mov.b64 {%0, %1}, %2;" : "=f"(lo), "=f"(hi) : "l"(v));
    return lo + hi;
}
__device__ __forceinline__ void cp16(uint32_t dst, const void* src) {
    asm volatile("cp.async.cg.shared.global [%0], [%1], 16;" :: "r"(dst), "l"(src));
}
#define CP_COMMIT()  asm volatile("cp.async.commit_group;" ::: "memory")
#define CP_WAIT(N)   asm volatile("cp.async.wait_group %0;" :: "n"(N) : "memory")

struct Buf {
    u64 k[4];
    u64 v[4];
    bool ok;
};

struct WState {
    u64 q2[GG][4];
    u64 acc[GG][4];
    float l[GG];
};

// kv stage buffer and post-loop reduction scratch are temporally disjoint -> union
union SmemU {
    float4 kv[NSTAGE * 8 * 64];            // 32 KB
    struct {
        float acc[4][GG][DD];              // 8 KB
        float l[4][GG];
    } red;
};

// Process one s position per half-warp (2 s per warp per call).
__device__ __forceinline__ void body(WState &st, const Buf &bf)
{
    float d[GG];
#pragma unroll
    for (int g = 0; g < GG; g++) {
        u64 t = pk(0.f, 0.f);
        fma2(t, st.q2[g][0], bf.k[0]);
        fma2(t, st.q2[g][1], bf.k[1]);
        fma2(t, st.q2[g][2], bf.k[2]);
        fma2(t, st.q2[g][3], bf.k[3]);
        d[g] = usum(t);
    }
#pragma unroll
    for (int off = 8; off > 0; off >>= 1) {
#pragma unroll
        for (int g = 0; g < GG; g++)
            d[g] += __shfl_xor_sync(0xffffffffu, d[g], off);
    }
#pragma unroll
    for (int g = 0; g < GG; g++) {
        float t = __expf(d[g] * C2_F);
        float p = __expf(__fdividef(-60.0f, t + 1.0f));
        p = bf.ok ? p : 0.0f;
        st.l[g] += p;
        u64 pp = pk(p, p);
        fma2(st.acc[g][0], pp, bf.v[0]);
        fma2(st.acc[g][1], pp, bf.v[1]);
        fma2(st.acc[g][2], pp, bf.v[2]);
        fma2(st.acc[g][3], pp, bf.v[3]);
    }
}

__global__ void __launch_bounds__(128, 5)
attn_partial_kernel(const float* __restrict__ q,
                    const float* __restrict__ knew,
                    const float* __restrict__ vnew,
                    const float* __restrict__ kc,
                    const float* __restrict__ vc,
                    const int*   __restrict__ seq_lens)
{
    const int h     = blockIdx.x;
    const int split = blockIdx.y;
    const int b     = blockIdx.z;
    const int tid   = threadIdx.x;
    const int w     = tid >> 5;          // 4 warps
    const int lane  = tid & 31;
    const int half  = lane >> 4;
    const int lh    = lane & 15;
    const int dcol  = lh * 8;

    const int seq_len = seq_lens[b];
    const int start   = split * CHUNK;

    if (start >= seq_len) return;        // never read by the reduce

    __shared__ SmemU su;

    const size_t pbase = (((size_t)(b * HKVN + h) * NSPLIT) + split) * GG;

    WState st;
    {
        const float* qb = q + (size_t)b * HQN * DD + (size_t)h * GG * DD + dcol;
#pragma unroll
        for (int g = 0; g < GG; g++) {
            float4 qa = *(const float4*)(qb + (size_t)g * DD);
            float4 qc = *(const float4*)(qb + (size_t)g * DD + 4);
            st.q2[g][0] = pk(qa.x, qa.y);
            st.q2[g][1] = pk(qa.z, qa.w);
            st.q2[g][2] = pk(qc.x, qc.y);
            st.q2[g][3] = pk(qc.z, qc.w);
            st.acc[g][0] = st.acc[g][1] = st.acc[g][2] = st.acc[g][3] = pk(0.f, 0.f);
            st.l[g] = 0.f;
        }
    }

    const int end_c = min(start + CHUNK, seq_len - 1);   // cache rows only
    const float* kbase = kc + ((size_t)b * SS) * KVROW + (size_t)h * DD;
    const float* vbase = vc + ((size_t)b * SS) * KVROW + (size_t)h * DD;

    const int span = end_c - start;
    const int n_it = (span > 0) ? ((span + 7) >> 3) : 0;

    const uint32_t smem_kv = (uint32_t)__cvta_generic_to_shared(su.kv);

    // cooperative fetch of one stage (8 s rows of K and V, 8 KB), 4 x 16B per thread
#define ISSUE_STAGE(STG, SBASE)                                            \
    do {                                                                   \
        _Pragma("unroll")                                                  \
        for (int j = 0; j < 4; j++) {                                      \
            int ci  = tid + j * 128;        /* 0..511 */                   \
            int row = ci >> 6;                                             \
            int sub = ci & 63;                                             \
            int isv = sub >> 5;                                            \
            int col = sub & 31;                                            \
            int s   = (SBASE) + row;                                       \
            s = (s < end_c) ? s : (end_c - 1);                             \
            const float* srcp = (isv ? vbase : kbase) + (size_t)s * KVROW + col * 4; \
            uint32_t dst = smem_kv + (uint32_t)((((STG) * 8 + row) * 64 + isv * 32 + col) * 16); \
            cp16(dst, srcp);                                               \
        }                                                                  \
    } while (0)

    if (n_it > 0) {
        // prologue: fill NSTAGE-1 stages
#pragma unroll
        for (int p = 0; p < NSTAGE - 1; p++) {
            if (p < n_it) ISSUE_STAGE(p, start + p * 8);
            CP_COMMIT();
        }

        const int row = w * 2 + half;     // this half-warp's row within a stage
        for (int it = 0; it < n_it; it++) {
            CP_WAIT(NSTAGE - 2);
            __syncthreads();

            const int stg = it & (NSTAGE - 1);
            const float4* b4 = su.kv + (stg * 8 + row) * 64;
            float4 k0 = b4[lh * 2], k1 = b4[lh * 2 + 1];
            float4 v0 = b4[32 + lh * 2], v1 = b4[32 + lh * 2 + 1];
            Buf bf;
            bf.ok = (start + it * 8 + row) < end_c;
            bf.k[0] = pk(k0.x, k0.y); bf.k[1] = pk(k0.z, k0.w);
            bf.k[2] = pk(k1.x, k1.y); bf.k[3] = pk(k1.z, k1.w);
            bf.v[0] = pk(v0.x, v0.y); bf.v[1] = pk(v0.z, v0.w);
            bf.v[2] = pk(v1.x, v1.y); bf.v[3] = pk(v1.z, v1.w);
            body(st, bf);

            const int pf = it + NSTAGE - 1;
            if (pf < n_it) ISSUE_STAGE(pf & (NSTAGE - 1), start + pf * 8);
            CP_COMMIT();
        }
    }

    // new token (s = seq_len-1), handled once by warp 0 / half 0
    const int last = seq_len - 1;
    if (w == 0 && last >= start && last < start + CHUNK) {
        const float* kp = knew + ((size_t)b * HKVN + h) * DD + dcol;
        const float* vp = vnew + ((size_t)b * HKVN + h) * DD + dcol;
        Buf nb;
        nb.ok = (half == 0);
        float4 ka  = *(const float4*)(kp);
        float4 kc4 = *(const float4*)(kp + 4);
        float4 va  = *(const float4*)(vp);
        float4 vc4 = *(const float4*)(vp + 4);
        nb.k[0] = pk(ka.x, ka.y);   nb.k[1] = pk(ka.z, ka.w);
        nb.k[2] = pk(kc4.x, kc4.y); nb.k[3] = pk(kc4.z, kc4.w);
        nb.v[0] = pk(va.x, va.y);   nb.v[1] = pk(va.z, va.w);
        nb.v[2] = pk(vc4.x, vc4.y); nb.v[3] = pk(vc4.z, vc4.w);
        body(st, nb);
    }

    // fold halves (registers only)
#pragma unroll
    for (int g = 0; g < GG; g++) {
#pragma unroll
        for (int j = 0; j < 4; j++) {
            u64 o = __shfl_xor_sync(0xffffffffu, st.acc[g][j], 16);
            float2 a = *(float2*)&st.acc[g][j];
            float2 ob = *(float2*)&o;
            a.x += ob.x; a.y += ob.y;
            st.acc[g][j] = pk(a.x, a.y);
        }
        st.l[g] += __shfl_xor_sync(0xffffffffu, st.l[g], 16);
    }

    // union switchover: all cp.async drained, all warps past their kv reads
    CP_WAIT(0);
    __syncthreads();

    if (half == 0) {
#pragma unroll
        for (int g = 0; g < GG; g++) {
            u64* dst = (u64*)&su.red.acc[w][g][dcol];
#pragma unroll
            for (int j = 0; j < 4; j++) dst[j] = st.acc[g][j];
            if (lh == 0) su.red.l[w][g] = st.l[g];
        }
    }
    __syncthreads();

    // combine 4 warps -> split partial (plain sums; fixed softmax shift m=30)
    for (int i = tid; i < GG * DD; i += 128) {
        int g = i >> 7, d = i & 127;
        float a = su.red.acc[0][g][d] + su.red.acc[1][g][d]
                + su.red.acc[2][g][d] + su.red.acc[3][g][d];
        g_pacc[(pbase + g) * DD + d] = a;
    }
    if (tid < GG) {
        float L = su.red.l[0][tid] + su.red.l[1][tid]
                + su.red.l[2][tid] + su.red.l[3][tid];
        g_pl[pbase + tid] = L;
    }
#undef ISSUE_STAGE
}

// One CTA per (b,h,g) = 1024 CTAs. 4 warps split the 32 splits (8 each, predicated,
// fully unrolled -> 16 front-batched loads/thread); one smem combine stage.
__global__ void __launch_bounds__(128)
attn_reduce_kernel(float* __restrict__ out, const int* __restrict__ seq_lens)
{
    const int idx = blockIdx.x;          // [0, BB*HKVN*GG)
    const int g = idx & 3;
    const int h = (idx >> 2) & 7;
    const int b = idx >> 5;
    const int tid  = threadIdx.x;
    const int w    = tid >> 5;
    const int lane = tid & 31;
    const int d4   = lane * 4;

    const int seq_len = seq_lens[b];
    const int n_valid = min(NSPLIT, (seq_len + CHUNK - 1) / CHUNK);

    const size_t base = ((size_t)(b * HKVN + h) * NSPLIT) * GG + g;

    float denom = 0.f;
    float4 a = make_float4(0.f, 0.f, 0.f, 0.f);
#pragma unroll
    for (int it = 0; it < NSPLIT / 4; it++) {
        int i = w + it * 4;
        bool v = (i < n_valid);
        size_t slot = base + (size_t)i * GG;
        float l = v ? g_pl[slot] : 0.f;
        float4 aa = v ? *(const float4*)&g_pacc[slot * DD + d4]
                      : make_float4(0.f, 0.f, 0.f, 0.f);
        denom += l;
        a.x += aa.x; a.y += aa.y; a.z += aa.z; a.w += aa.w;
    }

    __shared__ float4 sa[4][32];
    __shared__ float  sl[4];
    sa[w][lane] = a;
    if (lane == 0) sl[w] = denom;
    __syncthreads();

    if (w == 0) {
        float4 t0 = sa[0][lane], t1 = sa[1][lane], t2 = sa[2][lane], t3 = sa[3][lane];
        float4 t;
        t.x = (t0.x + t1.x) + (t2.x + t3.x);
        t.y = (t0.y + t1.y) + (t2.y + t3.y);
        t.z = (t0.z + t1.z) + (t2.z + t3.z);
        t.w = (t0.w + t1.w) + (t2.w + t3.w);
        float inv = 1.0f / ((sl[0] + sl[1]) + (sl[2] + sl[3]));
        float4 o = make_float4(t.x * inv, t.y * inv, t.z * inv, t.w * inv);
        *(float4*)&out[(size_t)b * HQN * DD + (size_t)(h * GG + g) * DD + d4] = o;
    }
}

extern "C" void kernel_launch(void* const* d_in, const int* in_sizes, int n_in,
                              void* d_out, int out_size)
{
    const float* q    = (const float*)d_in[0];
    const float* knew = (const float*)d_in[1];
    const float* vnew = (const float*)d_in[2];
    const float* kc   = (const float*)d_in[3];
    const float* vc   = (const float*)d_in[4];
    const int*   sl   = (const int*)  d_in[5];
    float* out = (float*)d_out;

    dim3 grid(HKVN, NSPLIT, BB);
    attn_partial_kernel<<<grid, 128>>>(q, knew, vnew, kc, vc, sl);
    attn_reduce_kernel<<<BB * HKVN * GG, 128>>>(out, sl);
}

// round 12
// speedup vs baseline: 1.2194x; 1.0118x over previous
#include <cuda_runtime.h>
#include <math.h>
#include <stdint.h>

// Problem constants (fixed by the reference)
#define BB      32
#define SS      4096
#define HQN     32
#define HKVN    8
#define GG      4          // HQN / HKVN
#define DD      128
#define NSPLIT  32
#define CHUNK   (SS / NSPLIT)   // 128
#define KVROW   (HKVN * DD)     // 1024 floats between consecutive s rows
#define SCALE_F 0.088388347648318447f   // 1/sqrt(128)
// p = exp(sc - 30), sc = 30*tanh(dot*SCALE/30)  =>  p = exp(-60/(exp(dot*SCALE/15)+1))
#define C2_F    (SCALE_F / 15.0f)
#define NSTAGE  4          // cp.async pipeline depth (8 KB per stage)

// Split-KV scratch (no allocations -> __device__ globals)
__device__ float g_pacc[(size_t)BB * HKVN * NSPLIT * GG * DD];
__device__ float g_pl[(size_t)BB * HKVN * NSPLIT * GG];

typedef unsigned long long u64;

__device__ __forceinline__ void fma2(u64 &d, u64 a, u64 b) {
    asm("fma.rn.f32x2 %0, %1, %2, %0;" : "+l"(d) : "l"(a), "l"(b));
}
__device__ __forceinline__ u64 pk(float x, float y) {
    u64 r; asm("mov.b64 %0, {%1, %2};" : "=l"(r) : "f"(x), "f"(y)); return r;
}
__device__ __forceinline__ float usum(u64 v) {
    float lo, hi; asm("mov.b64 {%0, %1}, %2;" : "=f"(lo), "=f"(hi) : "l"(v));
    return lo + hi;
}
// plain cp.async (the L2::cache_hint form traps on sm_103a - R11 post-mortem)
__device__ __forceinline__ void cp16(uint32_t dst, const void* src) {
    asm volatile("cp.async.cg.shared.global [%0], [%1], 16;" :: "r"(dst), "l"(src));
}
#define CP_COMMIT()  asm volatile("cp.async.commit_group;" ::: "memory")
#define CP_WAIT(N)   asm volatile("cp.async.wait_group %0;" :: "n"(N) : "memory")

struct Buf {
    u64 k[4];
    u64 v[4];
    bool ok;
};

struct WState {
    u64 q2[GG][4];
    u64 acc[GG][4];
    float l[GG];
};

// kv stage buffer and post-loop reduction scratch are temporally disjoint -> union
union SmemU {
    float4 kv[NSTAGE * 8 * 64];            // 32 KB
    struct {
        float acc[4][GG][DD];              // 8 KB
        float l[4][GG];
    } red;
};

// Process one s position per half-warp (2 s per warp per call).
__device__ __forceinline__ void body(WState &st, const Buf &bf)
{
    float d[GG];
#pragma unroll
    for (int g = 0; g < GG; g++) {
        u64 t = pk(0.f, 0.f);
        fma2(t, st.q2[g][0], bf.k[0]);
        fma2(t, st.q2[g][1], bf.k[1]);
        fma2(t, st.q2[g][2], bf.k[2]);
        fma2(t, st.q2[g][3], bf.k[3]);
        d[g] = usum(t);
    }
#pragma unroll
    for (int off = 8; off > 0; off >>= 1) {
#pragma unroll
        for (int g = 0; g < GG; g++)
            d[g] += __shfl_xor_sync(0xffffffffu, d[g], off);
    }
#pragma unroll
    for (int g = 0; g < GG; g++) {
        float t = __expf(d[g] * C2_F);
        float p = __expf(__fdividef(-60.0f, t + 1.0f));
        p = bf.ok ? p : 0.0f;
        st.l[g] += p;
        u64 pp = pk(p, p);
        fma2(st.acc[g][0], pp, bf.v[0]);
        fma2(st.acc[g][1], pp, bf.v[1]);
        fma2(st.acc[g][2], pp, bf.v[2]);
        fma2(st.acc[g][3], pp, bf.v[3]);
    }
}

__global__ void __launch_bounds__(128, 5)
attn_partial_kernel(const float* __restrict__ q,
                    const float* __restrict__ knew,
                    const float* __restrict__ vnew,
                    const float* __restrict__ kc,
                    const float* __restrict__ vc,
                    const int*   __restrict__ seq_lens)
{
    const int h     = blockIdx.x;
    const int split = blockIdx.y;
    const int b     = blockIdx.z;
    const int tid   = threadIdx.x;
    const int w     = tid >> 5;          // 4 warps
    const int lane  = tid & 31;
    const int half  = lane >> 4;
    const int lh    = lane & 15;
    // conflict-free lane ownership: float4 idx lh and 16+lh
    const int dcolA = lh * 4;            // d columns [dcolA, dcolA+4)
    const int dcolB = 64 + lh * 4;       // d columns [dcolB, dcolB+4)

    const int seq_len = seq_lens[b];
    const int start   = split * CHUNK;

    if (start >= seq_len) return;        // never read by the reduce

    __shared__ SmemU su;

    const size_t pbase = (((size_t)(b * HKVN + h) * NSPLIT) + split) * GG;

    WState st;
    {
        const float* qb = q + (size_t)b * HQN * DD + (size_t)h * GG * DD;
#pragma unroll
        for (int g = 0; g < GG; g++) {
            float4 qa = *(const float4*)(qb + (size_t)g * DD + dcolA);
            float4 qc = *(const float4*)(qb + (size_t)g * DD + dcolB);
            st.q2[g][0] = pk(qa.x, qa.y);
            st.q2[g][1] = pk(qa.z, qa.w);
            st.q2[g][2] = pk(qc.x, qc.y);
            st.q2[g][3] = pk(qc.z, qc.w);
            st.acc[g][0] = st.acc[g][1] = st.acc[g][2] = st.acc[g][3] = pk(0.f, 0.f);
            st.l[g] = 0.f;
        }
    }

    const int end_c = min(start + CHUNK, seq_len - 1);   // cache rows only
    const float* kbase = kc + ((size_t)b * SS) * KVROW + (size_t)h * DD;
    const float* vbase = vc + ((size_t)b * SS) * KVROW + (size_t)h * DD;

    const int span = end_c - start;
    const int n_it = (span > 0) ? ((span + 7) >> 3) : 0;

    const uint32_t smem_kv = (uint32_t)__cvta_generic_to_shared(su.kv);

    // cooperative fetch of one stage (8 s rows of K and V, 8 KB), 4 x 16B per thread
#define ISSUE_STAGE(STG, SBASE)                                            \
    do {                                                                   \
        _Pragma("unroll")                                                  \
        for (int j = 0; j < 4; j++) {                                      \
            int ci  = tid + j * 128;        /* 0..511 */                   \
            int row = ci >> 6;                                             \
            int sub = ci & 63;                                             \
            int isv = sub >> 5;                                            \
            int col = sub & 31;                                            \
            int s   = (SBASE) + row;                                       \
            s = (s < end_c) ? s : (end_c - 1);                             \
            const float* srcp = (isv ? vbase : kbase) + (size_t)s * KVROW + col * 4; \
            uint32_t dst = smem_kv + (uint32_t)((((STG) * 8 + row) * 64 + isv * 32 + col) * 16); \
            cp16(dst, srcp);                                               \
        }                                                                  \
    } while (0)

    if (n_it > 0) {
        // prologue: fill NSTAGE-1 stages
#pragma unroll
        for (int p = 0; p < NSTAGE - 1; p++) {
            if (p < n_it) ISSUE_STAGE(p, start + p * 8);
            CP_COMMIT();
        }

        const int row = w * 2 + half;     // this half-warp's row within a stage
        for (int it = 0; it < n_it; it++) {
            CP_WAIT(NSTAGE - 2);
            __syncthreads();

            const int stg = it & (NSTAGE - 1);
            const float4* b4 = su.kv + (stg * 8 + row) * 64;
            // conflict-free: 8 consecutive lanes read 128 contiguous bytes
            float4 k0 = b4[lh],      k1 = b4[16 + lh];
            float4 v0 = b4[32 + lh], v1 = b4[48 + lh];
            Buf bf;
            bf.ok = (start + it * 8 + row) < end_c;
            bf.k[0] = pk(k0.x, k0.y); bf.k[1] = pk(k0.z, k0.w);
            bf.k[2] = pk(k1.x, k1.y); bf.k[3] = pk(k1.z, k1.w);
            bf.v[0] = pk(v0.x, v0.y); bf.v[1] = pk(v0.z, v0.w);
            bf.v[2] = pk(v1.x, v1.y); bf.v[3] = pk(v1.z, v1.w);
            body(st, bf);

            const int pf = it + NSTAGE - 1;
            if (pf < n_it) ISSUE_STAGE(pf & (NSTAGE - 1), start + pf * 8);
            CP_COMMIT();
        }
    }

    // new token (s = seq_len-1), handled once by warp 0 / half 0
    const int last = seq_len - 1;
    if (w == 0 && last >= start && last < start + CHUNK) {
        const float* kp = knew + ((size_t)b * HKVN + h) * DD;
        const float* vp = vnew + ((size_t)b * HKVN + h) * DD;
        Buf nb;
        nb.ok = (half == 0);
        float4 ka  = *(const float4*)(kp + dcolA);
        float4 kc4 = *(const float4*)(kp + dcolB);
        float4 va  = *(const float4*)(vp + dcolA);
        float4 vc4 = *(const float4*)(vp + dcolB);
        nb.k[0] = pk(ka.x, ka.y);   nb.k[1] = pk(ka.z, ka.w);
        nb.k[2] = pk(kc4.x, kc4.y); nb.k[3] = pk(kc4.z, kc4.w);
        nb.v[0] = pk(va.x, va.y);   nb.v[1] = pk(va.z, va.w);
        nb.v[2] = pk(vc4.x, vc4.y); nb.v[3] = pk(vc4.z, vc4.w);
        body(st, nb);
    }

    // fold halves (registers only)
#pragma unroll
    for (int g = 0; g < GG; g++) {
#pragma unroll
        for (int j = 0; j < 4; j++) {
            u64 o = __shfl_xor_sync(0xffffffffu, st.acc[g][j], 16);
            float2 a = *(float2*)&st.acc[g][j];
            float2 ob = *(float2*)&o;
            a.x += ob.x; a.y += ob.y;
            st.acc[g][j] = pk(a.x, a.y);
        }
        st.l[g] += __shfl_xor_sync(0xffffffffu, st.l[g], 16);
    }

    // union switchover: all cp.async drained, all warps past their kv reads
    CP_WAIT(0);
    __syncthreads();

    if (half == 0) {
#pragma unroll
        for (int g = 0; g < GG; g++) {
            u64* dstA = (u64*)&su.red.acc[w][g][dcolA];
            u64* dstB = (u64*)&su.red.acc[w][g][dcolB];
            dstA[0] = st.acc[g][0]; dstA[1] = st.acc[g][1];
            dstB[0] = st.acc[g][2]; dstB[1] = st.acc[g][3];
            if (lh == 0) su.red.l[w][g] = st.l[g];
        }
    }
    __syncthreads();

    // combine 4 warps -> split partial (plain sums; fixed softmax shift m=30)
    for (int i = tid; i < GG * DD; i += 128) {
        int g = i >> 7, d = i & 127;
        float a = su.red.acc[0][g][d] + su.red.acc[1][g][d]
                + su.red.acc[2][g][d] + su.red.acc[3][g][d];
        g_pacc[(pbase + g) * DD + d] = a;
    }
    if (tid < GG) {
        float L = su.red.l[0][tid] + su.red.l[1][tid]
                + su.red.l[2][tid] + su.red.l[3][tid];
        g_pl[pbase + tid] = L;
    }
#undef ISSUE_STAGE
}

// One CTA per (b,h,g) = 1024 CTAs, 256 threads. 8 warps split the 32 splits
// (4 each, predicated, fully unrolled); one smem combine stage.
__global__ void __launch_bounds__(256)
attn_reduce_kernel(float* __restrict__ out, const int* __restrict__ seq_lens)
{
    const int idx = blockIdx.x;          // [0, BB*HKVN*GG)
    const int g = idx & 3;
    const int h = (idx >> 2) & 7;
    const int b = idx >> 5;
    const int tid  = threadIdx.x;
    const int w    = tid >> 5;           // 8 warps
    const int lane = tid & 31;
    const int d4   = lane * 4;

    const int seq_len = seq_lens[b];
    const int n_valid = min(NSPLIT, (seq_len + CHUNK - 1) / CHUNK);

    const size_t base = ((size_t)(b * HKVN + h) * NSPLIT) * GG + g;

    float denom = 0.f;
    float4 a = make_float4(0.f, 0.f, 0.f, 0.f);
#pragma unroll
    for (int it = 0; it < NSPLIT / 8; it++) {
        int i = w + it * 8;
        bool v = (i < n_valid);
        size_t slot = base + (size_t)i * GG;
        float l = v ? g_pl[slot] : 0.f;
        float4 aa = v ? *(const float4*)&g_pacc[slot * DD + d4]
                      : make_float4(0.f, 0.f, 0.f, 0.f);
        denom += l;
        a.x += aa.x; a.y += aa.y; a.z += aa.z; a.w += aa.w;
    }

    __shared__ float4 sa[8][32];
    __shared__ float  sl[8];
    sa[w][lane] = a;
    if (lane == 0) sl[w] = denom;
    __syncthreads();

    if (w == 0) {
        float4 t = sa[0][lane];
        float L = sl[0];
#pragma unroll
        for (int k = 1; k < 8; k++) {
            float4 u = sa[k][lane];
            t.x += u.x; t.y += u.y; t.z += u.z; t.w += u.w;
            L += sl[k];
        }
        float inv = 1.0f / L;
        float4 o = make_float4(t.x * inv, t.y * inv, t.z * inv, t.w * inv);
        *(float4*)&out[(size_t)b * HQN * DD + (size_t)(h * GG + g) * DD + d4] = o;
    }
}

extern "C" void kernel_launch(void* const* d_in, const int* in_sizes, int n_in,
                              void* d_out, int out_size)
{
    const float* q    = (const float*)d_in[0];
    const float* knew = (const float*)d_in[1];
    const float* vnew = (const float*)d_in[2];
    const float* kc   = (const float*)d_in[3];
    const float* vc   = (const float*)d_in[4];
    const int*   sl   = (const int*)  d_in[5];
    float* out = (float*)d_out;

    dim3 grid(HKVN, NSPLIT, BB);
    attn_partial_kernel<<<grid, 128>>>(q, knew, vnew, kc, vc, sl);
    attn_reduce_kernel<<<BB * HKVN * GG, 256>>>(out, sl);
}

// round 13
// speedup vs baseline: 1.2330x; 1.0112x over previous
#include <cuda_runtime.h>
#include <math.h>
#include <stdint.h>

// Problem constants (fixed by the reference)
#define BB      32
#define SS      4096
#define HQN     32
#define HKVN    8
#define GG      4          // HQN / HKVN
#define DD      128
#define NSPLIT  32
#define CHUNK   (SS / NSPLIT)   // 128
#define KVROW   (HKVN * DD)     // 1024 floats between consecutive s rows
#define SCALE_F 0.088388347648318447f   // 1/sqrt(128)
// p = exp(sc - 30), sc = 30*tanh(dot*SCALE/30)  =>  p = exp(-60/(exp(dot*SCALE/15)+1))
#define C2_F    (SCALE_F / 15.0f)
#define NSTAGE  4          // cp.async pipeline depth (8 KB per stage)

// Split-KV scratch (no allocations -> __device__ globals)
__device__ float g_pacc[(size_t)BB * HKVN * NSPLIT * GG * DD];
__device__ float g_pl[(size_t)BB * HKVN * NSPLIT * GG];

typedef unsigned long long u64;

__device__ __forceinline__ void fma2(u64 &d, u64 a, u64 b) {
    asm("fma.rn.f32x2 %0, %1, %2, %0;" : "+l"(d) : "l"(a), "l"(b));
}
__device__ __forceinline__ u64 pk(float x, float y) {
    u64 r; asm("mov.b64 %0, {%1, %2};" : "=l"(r) : "f"(x), "f"(y)); return r;
}
__device__ __forceinline__ float usum(u64 v) {
    float lo, hi; asm("mov.b64 {%0, %1}, %2;" : "=f"(lo), "=f"(hi) : "l"(v));
    return lo + hi;
}
// plain cp.async (the L2::cache_hint form traps on sm_103a - R11 post-mortem)
__device__ __forceinline__ void cp16(uint32_t dst, const void* src) {
    asm volatile("cp.async.cg.shared.global [%0], [%1], 16;" :: "r"(dst), "l"(src));
}
#define CP_COMMIT()  asm volatile("cp.async.commit_group;" ::: "memory")
#define CP_WAIT(N)   asm volatile("cp.async.wait_group %0;" :: "n"(N) : "memory")

struct Buf {
    u64 k[4];
    u64 v[4];
    bool ok;
};

struct WState {
    u64 q2[GG][4];
    u64 acc[GG][4];
    float l[GG];
};

// kv stage buffer and post-loop reduction scratch are temporally disjoint -> union
union SmemU {
    float4 kv[NSTAGE * 8 * 64];            // 32 KB
    struct {
        float acc[4][GG][DD];              // 8 KB
        float l[4][GG];
    } red;
};

// Process one s position per half-warp (2 s per warp per call).
__device__ __forceinline__ void body(WState &st, const Buf &bf)
{
    float d[GG];
#pragma unroll
    for (int g = 0; g < GG; g++) {
        u64 t = pk(0.f, 0.f);
        fma2(t, st.q2[g][0], bf.k[0]);
        fma2(t, st.q2[g][1], bf.k[1]);
        fma2(t, st.q2[g][2], bf.k[2]);
        fma2(t, st.q2[g][3], bf.k[3]);
        d[g] = usum(t);
    }
#pragma unroll
    for (int off = 8; off > 0; off >>= 1) {
#pragma unroll
        for (int g = 0; g < GG; g++)
            d[g] += __shfl_xor_sync(0xffffffffu, d[g], off);
    }
#pragma unroll
    for (int g = 0; g < GG; g++) {
        float t = __expf(d[g] * C2_F);
        float p = __expf(__fdividef(-60.0f, t + 1.0f));
        p = bf.ok ? p : 0.0f;
        st.l[g] += p;
        u64 pp = pk(p, p);
        fma2(st.acc[g][0], pp, bf.v[0]);
        fma2(st.acc[g][1], pp, bf.v[1]);
        fma2(st.acc[g][2], pp, bf.v[2]);
        fma2(st.acc[g][3], pp, bf.v[3]);
    }
}

__global__ void __launch_bounds__(128, 5)
attn_partial_kernel(const float* __restrict__ q,
                    const float* __restrict__ knew,
                    const float* __restrict__ vnew,
                    const float* __restrict__ kc,
                    const float* __restrict__ vc,
                    const int*   __restrict__ seq_lens)
{
    const int h     = blockIdx.x;
    const int split = blockIdx.y;
    const int b     = blockIdx.z;
    const int tid   = threadIdx.x;
    const int w     = tid >> 5;          // 4 warps
    const int lane  = tid & 31;
    const int half  = lane >> 4;
    const int lh    = lane & 15;
    // conflict-free lane ownership: float4 idx lh and 16+lh
    const int dcolA = lh * 4;            // d columns [dcolA, dcolA+4)
    const int dcolB = 64 + lh * 4;       // d columns [dcolB, dcolB+4)

    const int seq_len = seq_lens[b];
    const int start   = split * CHUNK;

    if (start >= seq_len) return;        // never read by the reduce

    __shared__ SmemU su;

    const size_t pbase = (((size_t)(b * HKVN + h) * NSPLIT) + split) * GG;

    WState st;
    {
        const float* qb = q + (size_t)b * HQN * DD + (size_t)h * GG * DD;
#pragma unroll
        for (int g = 0; g < GG; g++) {
            float4 qa = *(const float4*)(qb + (size_t)g * DD + dcolA);
            float4 qc = *(const float4*)(qb + (size_t)g * DD + dcolB);
            st.q2[g][0] = pk(qa.x, qa.y);
            st.q2[g][1] = pk(qa.z, qa.w);
            st.q2[g][2] = pk(qc.x, qc.y);
            st.q2[g][3] = pk(qc.z, qc.w);
            st.acc[g][0] = st.acc[g][1] = st.acc[g][2] = st.acc[g][3] = pk(0.f, 0.f);
            st.l[g] = 0.f;
        }
    }

    const int end_c = min(start + CHUNK, seq_len - 1);   // cache rows only
    const float* kbase = kc + ((size_t)b * SS) * KVROW + (size_t)h * DD;
    const float* vbase = vc + ((size_t)b * SS) * KVROW + (size_t)h * DD;

    const int span = end_c - start;
    const int n_it = (span > 0) ? ((span + 7) >> 3) : 0;

    const uint32_t smem_kv = (uint32_t)__cvta_generic_to_shared(su.kv);

    // cooperative fetch of one stage (8 s rows of K and V, 8 KB), 4 x 16B per thread
#define ISSUE_STAGE(STG, SBASE)                                            \
    do {                                                                   \
        _Pragma("unroll")                                                  \
        for (int j = 0; j < 4; j++) {                                      \
            int ci  = tid + j * 128;        /* 0..511 */                   \
            int row = ci >> 6;                                             \
            int sub = ci & 63;                                             \
            int isv = sub >> 5;                                            \
            int col = sub & 31;                                            \
            int s   = (SBASE) + row;                                       \
            s = (s < end_c) ? s : (end_c - 1);                             \
            const float* srcp = (isv ? vbase : kbase) + (size_t)s * KVROW + col * 4; \
            uint32_t dst = smem_kv + (uint32_t)((((STG) * 8 + row) * 64 + isv * 32 + col) * 16); \
            cp16(dst, srcp);                                               \
        }                                                                  \
    } while (0)

    if (n_it > 0) {
        // prologue: fill NSTAGE-1 stages
#pragma unroll
        for (int p = 0; p < NSTAGE - 1; p++) {
            if (p < n_it) ISSUE_STAGE(p, start + p * 8);
            CP_COMMIT();
        }

        const int row = w * 2 + half;     // this half-warp's row within a stage
        for (int it = 0; it < n_it; it++) {
            CP_WAIT(NSTAGE - 2);
            __syncthreads();

            const int stg = it & (NSTAGE - 1);
            const float4* b4 = su.kv + (stg * 8 + row) * 64;
            // conflict-free: 8 consecutive lanes read 128 contiguous bytes
            float4 k0 = b4[lh],      k1 = b4[16 + lh];
            float4 v0 = b4[32 + lh], v1 = b4[48 + lh];
            Buf bf;
            bf.ok = (start + it * 8 + row) < end_c;
            bf.k[0] = pk(k0.x, k0.y); bf.k[1] = pk(k0.z, k0.w);
            bf.k[2] = pk(k1.x, k1.y); bf.k[3] = pk(k1.z, k1.w);
            bf.v[0] = pk(v0.x, v0.y); bf.v[1] = pk(v0.z, v0.w);
            bf.v[2] = pk(v1.x, v1.y); bf.v[3] = pk(v1.z, v1.w);
            body(st, bf);

            const int pf = it + NSTAGE - 1;
            if (pf < n_it) ISSUE_STAGE(pf & (NSTAGE - 1), start + pf * 8);
            CP_COMMIT();
        }
    }

    // new token (s = seq_len-1), handled once by warp 0 / half 0
    const int last = seq_len - 1;
    if (w == 0 && last >= start && last < start + CHUNK) {
        const float* kp = knew + ((size_t)b * HKVN + h) * DD;
        const float* vp = vnew + ((size_t)b * HKVN + h) * DD;
        Buf nb;
        nb.ok = (half == 0);
        float4 ka  = *(const float4*)(kp + dcolA);
        float4 kc4 = *(const float4*)(kp + dcolB);
        float4 va  = *(const float4*)(vp + dcolA);
        float4 vc4 = *(const float4*)(vp + dcolB);
        nb.k[0] = pk(ka.x, ka.y);   nb.k[1] = pk(ka.z, ka.w);
        nb.k[2] = pk(kc4.x, kc4.y); nb.k[3] = pk(kc4.z, kc4.w);
        nb.v[0] = pk(va.x, va.y);   nb.v[1] = pk(va.z, va.w);
        nb.v[2] = pk(vc4.x, vc4.y); nb.v[3] = pk(vc4.z, vc4.w);
        body(st, nb);
    }

    // fold halves (registers only)
#pragma unroll
    for (int g = 0; g < GG; g++) {
#pragma unroll
        for (int j = 0; j < 4; j++) {
            u64 o = __shfl_xor_sync(0xffffffffu, st.acc[g][j], 16);
            float2 a = *(float2*)&st.acc[g][j];
            float2 ob = *(float2*)&o;
            a.x += ob.x; a.y += ob.y;
            st.acc[g][j] = pk(a.x, a.y);
        }
        st.l[g] += __shfl_xor_sync(0xffffffffu, st.l[g], 16);
    }

    // union switchover: all cp.async drained, all warps past their kv reads
    CP_WAIT(0);
    __syncthreads();

    if (half == 0) {
#pragma unroll
        for (int g = 0; g < GG; g++) {
            u64* dstA = (u64*)&su.red.acc[w][g][dcolA];
            u64* dstB = (u64*)&su.red.acc[w][g][dcolB];
            dstA[0] = st.acc[g][0]; dstA[1] = st.acc[g][1];
            dstB[0] = st.acc[g][2]; dstB[1] = st.acc[g][3];
            if (lh == 0) su.red.l[w][g] = st.l[g];
        }
    }
    __syncthreads();

    // combine 4 warps -> split partial (plain sums; fixed softmax shift m=30)
    for (int i = tid; i < GG * DD; i += 128) {
        int g = i >> 7, d = i & 127;
        float a = su.red.acc[0][g][d] + su.red.acc[1][g][d]
                + su.red.acc[2][g][d] + su.red.acc[3][g][d];
        g_pacc[(pbase + g) * DD + d] = a;
    }
    if (tid < GG) {
        float L = su.red.l[0][tid] + su.red.l[1][tid]
                + su.red.l[2][tid] + su.red.l[3][tid];
        g_pl[pbase + tid] = L;
    }
#undef ISSUE_STAGE
}

// One CTA per (b,h,g) = 1024 CTAs, 256 threads. 8 warps split the 32 splits
// (4 each). Loads are UNCONDITIONAL (index clamped to a valid slot) so ptxas
// front-batches all of them; validity folds in as a multiplicative weight.
__global__ void __launch_bounds__(256)
attn_reduce_kernel(float* __restrict__ out, const int* __restrict__ seq_lens)
{
    const int idx = blockIdx.x;          // [0, BB*HKVN*GG)
    const int g = idx & 3;
    const int h = (idx >> 2) & 7;
    const int b = idx >> 5;
    const int tid  = threadIdx.x;
    const int w    = tid >> 5;           // 8 warps
    const int lane = tid & 31;
    const int d4   = lane * 4;

    const int seq_len = seq_lens[b];
    const int n_valid = min(NSPLIT, (seq_len + CHUNK - 1) / CHUNK);

    const size_t base = ((size_t)(b * HKVN + h) * NSPLIT) * GG + g;

    float denom = 0.f;
    float4 a = make_float4(0.f, 0.f, 0.f, 0.f);
#pragma unroll
    for (int it = 0; it < NSPLIT / 8; it++) {
        int i  = w + it * 8;
        int ic = min(i, n_valid - 1);            // always a valid slot
        float wv = (i < n_valid) ? 1.f : 0.f;    // validity as weight
        size_t slot = base + (size_t)ic * GG;
        float l   = g_pl[slot];                  // unconditional
        float4 aa = *(const float4*)&g_pacc[slot * DD + d4];  // unconditional
        denom = fmaf(wv, l, denom);
        a.x = fmaf(wv, aa.x, a.x);
        a.y = fmaf(wv, aa.y, a.y);
        a.z = fmaf(wv, aa.z, a.z);
        a.w = fmaf(wv, aa.w, a.w);
    }

    __shared__ float4 sa[8][32];
    __shared__ float  sl[8];
    sa[w][lane] = a;
    if (lane == 0) sl[w] = denom;
    __syncthreads();

    if (w == 0) {
        float4 t = sa[0][lane];
        float L = sl[0];
#pragma unroll
        for (int k = 1; k < 8; k++) {
            float4 u = sa[k][lane];
            t.x += u.x; t.y += u.y; t.z += u.z; t.w += u.w;
            L += sl[k];
        }
        float inv = 1.0f / L;
        float4 o = make_float4(t.x * inv, t.y * inv, t.z * inv, t.w * inv);
        *(float4*)&out[(size_t)b * HQN * DD + (size_t)(h * GG + g) * DD + d4] = o;
    }
}

extern "C" void kernel_launch(void* const* d_in, const int* in_sizes, int n_in,
                              void* d_out, int out_size)
{
    const float* q    = (const float*)d_in[0];
    const float* knew = (const float*)d_in[1];
    const float* vnew = (const float*)d_in[2];
    const float* kc   = (const float*)d_in[3];
    const float* vc   = (const float*)d_in[4];
    const int*   sl   = (const int*)  d_in[5];
    float* out = (float*)d_out;

    dim3 grid(HKVN, NSPLIT, BB);
    attn_partial_kernel<<<grid, 128>>>(q, knew, vnew, kc, vc, sl);
    attn_reduce_kernel<<<BB * HKVN * GG, 256>>>(out, sl);
}

// round 14
// speedup vs baseline: 1.2928x; 1.0485x over previous
#include <cuda_runtime.h>
#include <math.h>
#include <stdint.h>

// Problem constants (fixed by the reference)
#define BB      32
#define SS      4096
#define HQN     32
#define HKVN    8
#define GG      4          // HQN / HKVN
#define DD      128
#define NSPLIT  32
#define CHUNK   (SS / NSPLIT)   // 128
#define KVROW   (HKVN * DD)     // 1024 floats between consecutive s rows
#define SCALE_F 0.088388347648318447f   // 1/sqrt(128)
// p = exp(sc - 30), sc = 30*tanh(dot*SCALE/30)  =>  p = exp(-60/(exp(dot*SCALE/15)+1))
#define C2_F    (SCALE_F / 15.0f)
#define NSTAGE  4          // cp.async pipeline depth (8 KB per stage)

// Dense accumulators (fixed softmax shift m=30 -> combination is LINEAR).
// Zero-initialized at module load; the divide kernel resets them to zero after
// each use, so every graph replay sees zeros. No allocations -> __device__.
__device__ float g_oacc[(size_t)BB * HKVN * GG * DD];   // 512 KB
__device__ float g_lacc[(size_t)BB * HKVN * GG];

typedef unsigned long long u64;

__device__ __forceinline__ void fma2(u64 &d, u64 a, u64 b) {
    asm("fma.rn.f32x2 %0, %1, %2, %0;" : "+l"(d) : "l"(a), "l"(b));
}
__device__ __forceinline__ u64 pk(float x, float y) {
    u64 r; asm("mov.b64 %0, {%1, %2};" : "=l"(r) : "f"(x), "f"(y)); return r;
}
__device__ __forceinline__ float usum(u64 v) {
    float lo, hi; asm("mov.b64 {%0, %1}, %2;" : "=f"(lo), "=f"(hi) : "l"(v));
    return lo + hi;
}
// plain cp.async (the L2::cache_hint form traps on sm_103a - R11 post-mortem)
__device__ __forceinline__ void cp16(uint32_t dst, const void* src) {
    asm volatile("cp.async.cg.shared.global [%0], [%1], 16;" :: "r"(dst), "l"(src));
}
#define CP_COMMIT()  asm volatile("cp.async.commit_group;" ::: "memory")
#define CP_WAIT(N)   asm volatile("cp.async.wait_group %0;" :: "n"(N) : "memory")

struct Buf {
    u64 k[4];
    u64 v[4];
    bool ok;
};

struct WState {
    u64 q2[GG][4];
    u64 acc[GG][4];
    float l[GG];
};

// kv stage buffer and post-loop reduction scratch are temporally disjoint -> union
union SmemU {
    float4 kv[NSTAGE * 8 * 64];            // 32 KB
    struct {
        float acc[4][GG][DD];              // 8 KB
        float l[4][GG];
    } red;
};

// Process one s position per half-warp (2 s per warp per call).
__device__ __forceinline__ void body(WState &st, const Buf &bf)
{
    float d[GG];
#pragma unroll
    for (int g = 0; g < GG; g++) {
        u64 t = pk(0.f, 0.f);
        fma2(t, st.q2[g][0], bf.k[0]);
        fma2(t, st.q2[g][1], bf.k[1]);
        fma2(t, st.q2[g][2], bf.k[2]);
        fma2(t, st.q2[g][3], bf.k[3]);
        d[g] = usum(t);
    }
#pragma unroll
    for (int off = 8; off > 0; off >>= 1) {
#pragma unroll
        for (int g = 0; g < GG; g++)
            d[g] += __shfl_xor_sync(0xffffffffu, d[g], off);
    }
#pragma unroll
    for (int g = 0; g < GG; g++) {
        float t = __expf(d[g] * C2_F);
        float p = __expf(__fdividef(-60.0f, t + 1.0f));
        p = bf.ok ? p : 0.0f;
        st.l[g] += p;
        u64 pp = pk(p, p);
        fma2(st.acc[g][0], pp, bf.v[0]);
        fma2(st.acc[g][1], pp, bf.v[1]);
        fma2(st.acc[g][2], pp, bf.v[2]);
        fma2(st.acc[g][3], pp, bf.v[3]);
    }
}

__global__ void __launch_bounds__(128, 5)
attn_partial_kernel(const float* __restrict__ q,
                    const float* __restrict__ knew,
                    const float* __restrict__ vnew,
                    const float* __restrict__ kc,
                    const float* __restrict__ vc,
                    const int*   __restrict__ seq_lens)
{
    const int h     = blockIdx.x;
    const int split = blockIdx.y;
    const int b     = blockIdx.z;
    const int tid   = threadIdx.x;
    const int w     = tid >> 5;          // 4 warps
    const int lane  = tid & 31;
    const int half  = lane >> 4;
    const int lh    = lane & 15;
    // conflict-free lane ownership: float4 idx lh and 16+lh
    const int dcolA = lh * 4;            // d columns [dcolA, dcolA+4)
    const int dcolB = 64 + lh * 4;       // d columns [dcolB, dcolB+4)

    const int seq_len = seq_lens[b];
    const int start   = split * CHUNK;

    if (start >= seq_len) return;        // contributes nothing

    __shared__ SmemU su;

    WState st;
    {
        const float* qb = q + (size_t)b * HQN * DD + (size_t)h * GG * DD;
#pragma unroll
        for (int g = 0; g < GG; g++) {
            float4 qa = *(const float4*)(qb + (size_t)g * DD + dcolA);
            float4 qc = *(const float4*)(qb + (size_t)g * DD + dcolB);
            st.q2[g][0] = pk(qa.x, qa.y);
            st.q2[g][1] = pk(qa.z, qa.w);
            st.q2[g][2] = pk(qc.x, qc.y);
            st.q2[g][3] = pk(qc.z, qc.w);
            st.acc[g][0] = st.acc[g][1] = st.acc[g][2] = st.acc[g][3] = pk(0.f, 0.f);
            st.l[g] = 0.f;
        }
    }

    const int end_c = min(start + CHUNK, seq_len - 1);   // cache rows only
    const float* kbase = kc + ((size_t)b * SS) * KVROW + (size_t)h * DD;
    const float* vbase = vc + ((size_t)b * SS) * KVROW + (size_t)h * DD;

    const int span = end_c - start;
    const int n_it = (span > 0) ? ((span + 7) >> 3) : 0;

    const uint32_t smem_kv = (uint32_t)__cvta_generic_to_shared(su.kv);

    // cooperative fetch of one stage (8 s rows of K and V, 8 KB), 4 x 16B per thread
#define ISSUE_STAGE(STG, SBASE)                                            \
    do {                                                                   \
        _Pragma("unroll")                                                  \
        for (int j = 0; j < 4; j++) {                                      \
            int ci  = tid + j * 128;        /* 0..511 */                   \
            int row = ci >> 6;                                             \
            int sub = ci & 63;                                             \
            int isv = sub >> 5;                                            \
            int col = sub & 31;                                            \
            int s   = (SBASE) + row;                                       \
            s = (s < end_c) ? s : (end_c - 1);                             \
            const float* srcp = (isv ? vbase : kbase) + (size_t)s * KVROW + col * 4; \
            uint32_t dst = smem_kv + (uint32_t)((((STG) * 8 + row) * 64 + isv * 32 + col) * 16); \
            cp16(dst, srcp);                                               \
        }                                                                  \
    } while (0)

    if (n_it > 0) {
        // prologue: fill NSTAGE-1 stages
#pragma unroll
        for (int p = 0; p < NSTAGE - 1; p++) {
            if (p < n_it) ISSUE_STAGE(p, start + p * 8);
            CP_COMMIT();
        }

        const int row = w * 2 + half;     // this half-warp's row within a stage
        for (int it = 0; it < n_it; it++) {
            CP_WAIT(NSTAGE - 2);
            __syncthreads();

            const int stg = it & (NSTAGE - 1);
            const float4* b4 = su.kv + (stg * 8 + row) * 64;
            // conflict-free: 8 consecutive lanes read 128 contiguous bytes
            float4 k0 = b4[lh],      k1 = b4[16 + lh];
            float4 v0 = b4[32 + lh], v1 = b4[48 + lh];
            Buf bf;
            bf.ok = (start + it * 8 + row) < end_c;
            bf.k[0] = pk(k0.x, k0.y); bf.k[1] = pk(k0.z, k0.w);
            bf.k[2] = pk(k1.x, k1.y); bf.k[3] = pk(k1.z, k1.w);
            bf.v[0] = pk(v0.x, v0.y); bf.v[1] = pk(v0.z, v0.w);
            bf.v[2] = pk(v1.x, v1.y); bf.v[3] = pk(v1.z, v1.w);
            body(st, bf);

            const int pf = it + NSTAGE - 1;
            if (pf < n_it) ISSUE_STAGE(pf & (NSTAGE - 1), start + pf * 8);
            CP_COMMIT();
        }
    }

    // new token (s = seq_len-1), handled once by warp 0 / half 0
    const int last = seq_len - 1;
    if (w == 0 && last >= start && last < start + CHUNK) {
        const float* kp = knew + ((size_t)b * HKVN + h) * DD;
        const float* vp = vnew + ((size_t)b * HKVN + h) * DD;
        Buf nb;
        nb.ok = (half == 0);
        float4 ka  = *(const float4*)(kp + dcolA);
        float4 kc4 = *(const float4*)(kp + dcolB);
        float4 va  = *(const float4*)(vp + dcolA);
        float4 vc4 = *(const float4*)(vp + dcolB);
        nb.k[0] = pk(ka.x, ka.y);   nb.k[1] = pk(ka.z, ka.w);
        nb.k[2] = pk(kc4.x, kc4.y); nb.k[3] = pk(kc4.z, kc4.w);
        nb.v[0] = pk(va.x, va.y);   nb.v[1] = pk(va.z, va.w);
        nb.v[2] = pk(vc4.x, vc4.y); nb.v[3] = pk(vc4.z, vc4.w);
        body(st, nb);
    }

    // fold halves (registers only)
#pragma unroll
    for (int g = 0; g < GG; g++) {
#pragma unroll
        for (int j = 0; j < 4; j++) {
            u64 o = __shfl_xor_sync(0xffffffffu, st.acc[g][j], 16);
            float2 a = *(float2*)&st.acc[g][j];
            float2 ob = *(float2*)&o;
            a.x += ob.x; a.y += ob.y;
            st.acc[g][j] = pk(a.x, a.y);
        }
        st.l[g] += __shfl_xor_sync(0xffffffffu, st.l[g], 16);
    }

    // union switchover: all cp.async drained, all warps past their kv reads
    CP_WAIT(0);
    __syncthreads();

    if (half == 0) {
#pragma unroll
        for (int g = 0; g < GG; g++) {
            u64* dstA = (u64*)&su.red.acc[w][g][dcolA];
            u64* dstB = (u64*)&su.red.acc[w][g][dcolB];
            dstA[0] = st.acc[g][0]; dstA[1] = st.acc[g][1];
            dstB[0] = st.acc[g][2]; dstB[1] = st.acc[g][3];
            if (lh == 0) su.red.l[w][g] = st.l[g];
        }
    }
    __syncthreads();

    // combine 4 warps, then LINEAR atomic accumulation into the dense output
    // accumulator (fixed softmax shift m=30 makes split combination a plain sum)
    const size_t obase = ((size_t)(b * HKVN + h)) * GG;
    for (int i = tid; i < GG * DD; i += 128) {
        int g = i >> 7, d = i & 127;
        float a = su.red.acc[0][g][d] + su.red.acc[1][g][d]
                + su.red.acc[2][g][d] + su.red.acc[3][g][d];
        atomicAdd(&g_oacc[(obase + g) * DD + d], a);
    }
    if (tid < GG) {
        float L = su.red.l[0][tid] + su.red.l[1][tid]
                + su.red.l[2][tid] + su.red.l[3][tid];
        atomicAdd(&g_lacc[obase + tid], L);
    }
#undef ISSUE_STAGE
}

// Final divide + accumulator reset. One CTA per (b,h): 128 threads cover
// g (4) x lane (32) x 4 d-columns. Reads are L2-hot (just RED-written).
__global__ void __launch_bounds__(128)
attn_divide_kernel(float* __restrict__ out)
{
    const int bh = blockIdx.x;           // [0, BB*HKVN)
    const int h  = bh % HKVN;
    const int b  = bh / HKVN;
    const int tid  = threadIdx.x;
    const int g    = tid >> 5;
    const int lane = tid & 31;
    const int d4   = lane * 4;

    const size_t base = ((size_t)(b * HKVN + h)) * GG + g;

    float l = g_lacc[base];
    float4 a = *(const float4*)&g_oacc[base * DD + d4];
    float inv = 1.0f / l;
    float4 o = make_float4(a.x * inv, a.y * inv, a.z * inv, a.w * inv);
    *(float4*)&out[(size_t)b * HQN * DD + (size_t)(h * GG + g) * DD + d4] = o;

    // reset for the next graph replay (ordered after our reads; every slot
    // is covered exactly once across the grid)
    *(float4*)&g_oacc[base * DD + d4] = make_float4(0.f, 0.f, 0.f, 0.f);
    if (lane == 0) g_lacc[base] = 0.f;
}

extern "C" void kernel_launch(void* const* d_in, const int* in_sizes, int n_in,
                              void* d_out, int out_size)
{
    const float* q    = (const float*)d_in[0];
    const float* knew = (const float*)d_in[1];
    const float* vnew = (const float*)d_in[2];
    const float* kc   = (const float*)d_in[3];
    const float* vc   = (const float*)d_in[4];
    const int*   sl   = (const int*)  d_in[5];
    float* out = (float*)d_out;

    dim3 grid(HKVN, NSPLIT, BB);
    attn_partial_kernel<<<grid, 128>>>(q, knew, vnew, kc, vc, sl);
    attn_divide_kernel<<<BB * HKVN, 128>>>(out);
}